// round 1
// baseline (speedup 1.0000x reference)
#include <cuda_runtime.h>
#include <cstdint>

// Problem constants (fixed shapes)
constexpr int N_NODES = 8192;
constexpr int D = 512;
constexpr int E_EDGES = 131072;
constexpr int B_GR = 16;
constexpr int NPG = 512;
constexpr int S_SEL = 128;
constexpr int L_LAYERS = 3;

// -------- static device scratch (allocation-free rule) --------
__device__ float    g_x[N_NODES * D];
__device__ float    g_h[N_NODES * D];
__device__ float    g_A[N_NODES * D];
__device__ float    g_B[N_NODES * D];
__device__ unsigned g_agg[N_NODES * D];

// -------- float <-> monotone uint encoding for atomic max --------
__device__ __forceinline__ unsigned fenc(float f) {
    unsigned b = __float_as_uint(f);
    return (b & 0x80000000u) ? ~b : (b | 0x80000000u);
}
__device__ __forceinline__ float fdec(unsigned u) {
    unsigned b = (u & 0x80000000u) ? (u & 0x7fffffffu) : ~u;
    return __uint_as_float(b);
}

// ================= init: copy x, zero agg =================
__global__ void k_init(const float* __restrict__ x) {
    int i = blockIdx.x * 256 + threadIdx.x;
    g_x[i] = x[i];
    g_agg[i] = 0u;
}

// ================= LayerNorm (one block per row, 128 thr) =================
__global__ __launch_bounds__(128) void k_ln(const float* __restrict__ x,
                                            const float* __restrict__ gamma,
                                            const float* __restrict__ beta,
                                            float* __restrict__ out) {
    __shared__ float red[8];
    int row = blockIdx.x;
    int t = threadIdx.x;
    const float4* xr = (const float4*)(x + (size_t)row * D);
    float4 v = xr[t];

    float s = v.x + v.y + v.z + v.w;
    #pragma unroll
    for (int o = 16; o > 0; o >>= 1) s += __shfl_xor_sync(0xffffffffu, s, o);
    if ((t & 31) == 0) red[t >> 5] = s;
    __syncthreads();
    if (t == 0) red[4] = red[0] + red[1] + red[2] + red[3];
    __syncthreads();
    float mu = red[4] * (1.0f / D);
    __syncthreads();

    float dx = v.x - mu, dy = v.y - mu, dz = v.z - mu, dw = v.w - mu;
    float q = dx * dx + dy * dy + dz * dz + dw * dw;
    #pragma unroll
    for (int o = 16; o > 0; o >>= 1) q += __shfl_xor_sync(0xffffffffu, q, o);
    if ((t & 31) == 0) red[t >> 5] = q;
    __syncthreads();
    if (t == 0) red[4] = red[0] + red[1] + red[2] + red[3];
    __syncthreads();
    float rstd = rsqrtf(red[4] * (1.0f / D) + 1e-5f);

    float4 g4 = ((const float4*)gamma)[t];
    float4 b4 = ((const float4*)beta)[t];
    float4 o4;
    o4.x = dx * rstd * g4.x + b4.x;
    o4.y = dy * rstd * g4.y + b4.y;
    o4.z = dz * rstd * g4.z + b4.z;
    o4.w = dw * rstd * g4.w + b4.w;
    ((float4*)(out + (size_t)row * D))[t] = o4;
}

// ================= dual GEMM: A = H@(W1t - W1b) + b1 ; B = H@W1b =================
// Tiles: 128(M) x 64(N) x 16(K), 256 threads, micro 8x4 (two accumulator sets)
__global__ __launch_bounds__(256) void k_dualgemm(const float* __restrict__ H,
                                                  const float* __restrict__ W1,
                                                  const float* __restrict__ b1,
                                                  float* __restrict__ Aout,
                                                  float* __restrict__ Bout) {
    __shared__ float Hs[16][132];
    __shared__ float Wt[16][64];
    __shared__ float Wb[16][64];
    int m0 = blockIdx.x * 128, n0 = blockIdx.y * 64;
    int tid = threadIdx.x;
    int ty = tid >> 4, tx = tid & 15;
    float accA[8][4] = {}, accB[8][4] = {};

    for (int kk = 0; kk < D; kk += 16) {
        #pragma unroll
        for (int r = 0; r < 2; r++) {
            int t = tid + r * 256;
            int m = t >> 2, k4 = (t & 3) * 4;
            float4 v = *(const float4*)(H + (size_t)(m0 + m) * D + kk + k4);
            Hs[k4 + 0][m] = v.x; Hs[k4 + 1][m] = v.y;
            Hs[k4 + 2][m] = v.z; Hs[k4 + 3][m] = v.w;
        }
        {
            int kr = tid >> 4, c4 = (tid & 15) * 4;
            float4 wt = *(const float4*)(W1 + (size_t)(kk + kr) * D + n0 + c4);
            float4 wb = *(const float4*)(W1 + (size_t)(D + kk + kr) * D + n0 + c4);
            *(float4*)&Wt[kr][c4] = make_float4(wt.x - wb.x, wt.y - wb.y,
                                                wt.z - wb.z, wt.w - wb.w);
            *(float4*)&Wb[kr][c4] = wb;
        }
        __syncthreads();
        #pragma unroll
        for (int k = 0; k < 16; k++) {
            float h[8], wa[4], wbv[4];
            #pragma unroll
            for (int i = 0; i < 8; i++) h[i] = Hs[k][ty * 8 + i];
            #pragma unroll
            for (int j = 0; j < 4; j++) { wa[j] = Wt[k][tx * 4 + j]; wbv[j] = Wb[k][tx * 4 + j]; }
            #pragma unroll
            for (int i = 0; i < 8; i++)
                #pragma unroll
                for (int j = 0; j < 4; j++) {
                    accA[i][j] = fmaf(h[i], wa[j], accA[i][j]);
                    accB[i][j] = fmaf(h[i], wbv[j], accB[i][j]);
                }
        }
        __syncthreads();
    }
    #pragma unroll
    for (int i = 0; i < 8; i++) {
        size_t m = (size_t)(m0 + ty * 8 + i);
        #pragma unroll
        for (int j = 0; j < 4; j++) {
            int n = n0 + tx * 4 + j;
            Aout[m * D + n] = accA[i][j] + b1[n];
            Bout[m * D + n] = accB[i][j];
        }
    }
}

// ================= fused edge GEMM + segment-max =================
// M = relu(A[dst] + B[src]) @ W2 ; atomicMax into agg[dst].
// Tiles: 128(edges) x 128(N) x 16(K), 256 threads, micro 8x8.
__global__ __launch_bounds__(256) void k_edge(const float* __restrict__ Am,
                                              const float* __restrict__ Bm,
                                              const float* __restrict__ W2,
                                              const int* __restrict__ src,
                                              const int* __restrict__ dst,
                                              unsigned* __restrict__ agg) {
    __shared__ float Zs[16][132];
    __shared__ float Ws[16][128];
    __shared__ int sDst[128], sSrc[128];
    int e0 = blockIdx.x * 128, n0 = blockIdx.y * 128;
    int tid = threadIdx.x;
    if (tid < 128) { sDst[tid] = dst[e0 + tid]; sSrc[tid] = src[e0 + tid]; }
    __syncthreads();

    int ty = tid >> 4, tx = tid & 15;
    float acc[8][8] = {};

    for (int kk = 0; kk < D; kk += 16) {
        #pragma unroll
        for (int r = 0; r < 2; r++) {
            int t = tid + r * 256;
            int e = t >> 2, k4 = (t & 3) * 4;
            float4 a4 = *(const float4*)(Am + (size_t)sDst[e] * D + kk + k4);
            float4 b4 = *(const float4*)(Bm + (size_t)sSrc[e] * D + kk + k4);
            Zs[k4 + 0][e] = fmaxf(a4.x + b4.x, 0.f);
            Zs[k4 + 1][e] = fmaxf(a4.y + b4.y, 0.f);
            Zs[k4 + 2][e] = fmaxf(a4.z + b4.z, 0.f);
            Zs[k4 + 3][e] = fmaxf(a4.w + b4.w, 0.f);
        }
        #pragma unroll
        for (int r = 0; r < 2; r++) {
            int t = tid + r * 256;
            int kr = t >> 5, c4 = (t & 31) * 4;
            *(float4*)&Ws[kr][c4] = *(const float4*)(W2 + (size_t)(kk + kr) * D + n0 + c4);
        }
        __syncthreads();
        #pragma unroll
        for (int k = 0; k < 16; k++) {
            float av[8], bv[8];
            #pragma unroll
            for (int i = 0; i < 8; i++) av[i] = Zs[k][ty * 8 + i];
            #pragma unroll
            for (int j = 0; j < 8; j++) bv[j] = Ws[k][tx * 8 + j];
            #pragma unroll
            for (int i = 0; i < 8; i++)
                #pragma unroll
                for (int j = 0; j < 8; j++)
                    acc[i][j] = fmaf(av[i], bv[j], acc[i][j]);
        }
        __syncthreads();
    }
    #pragma unroll
    for (int i = 0; i < 8; i++) {
        int e = ty * 8 + i;
        unsigned* base = agg + (size_t)sDst[e] * D + n0 + tx * 8;
        #pragma unroll
        for (int j = 0; j < 8; j++)
            atomicMax(base + j, fenc(acc[i][j]));
    }
}

// ================= combine: x = max(dec(agg)+b2, 0) + x ; reset agg =================
__global__ void k_combine(const float* __restrict__ b2) {
    int i = blockIdx.x * 256 + threadIdx.x;
    unsigned u = g_agg[i];
    g_agg[i] = 0u;
    float v = (u == 0u) ? 0.0f : (fdec(u) + b2[i & (D - 1)]);
    g_x[i] = fmaxf(v, 0.0f) + g_x[i];
}

// ================= plain GEMM: C = op(A@W + bias [+res]) =================
// Tiles: 128 x 128 x 16, 256 threads, micro 8x8.
__global__ __launch_bounds__(256) void k_gemm(const float* __restrict__ A,
                                              const float* __restrict__ W,
                                              const float* __restrict__ bias,
                                              const float* __restrict__ res,
                                              float* __restrict__ C,
                                              int relu) {
    __shared__ float As[16][132];
    __shared__ float Ws[16][128];
    int m0 = blockIdx.x * 128, n0 = blockIdx.y * 128;
    int tid = threadIdx.x;
    int ty = tid >> 4, tx = tid & 15;
    float acc[8][8] = {};

    for (int kk = 0; kk < D; kk += 16) {
        #pragma unroll
        for (int r = 0; r < 2; r++) {
            int t = tid + r * 256;
            int m = t >> 2, k4 = (t & 3) * 4;
            float4 v = *(const float4*)(A + (size_t)(m0 + m) * D + kk + k4);
            As[k4 + 0][m] = v.x; As[k4 + 1][m] = v.y;
            As[k4 + 2][m] = v.z; As[k4 + 3][m] = v.w;
        }
        #pragma unroll
        for (int r = 0; r < 2; r++) {
            int t = tid + r * 256;
            int kr = t >> 5, c4 = (t & 31) * 4;
            *(float4*)&Ws[kr][c4] = *(const float4*)(W + (size_t)(kk + kr) * D + n0 + c4);
        }
        __syncthreads();
        #pragma unroll
        for (int k = 0; k < 16; k++) {
            float av[8], bv[8];
            #pragma unroll
            for (int i = 0; i < 8; i++) av[i] = As[k][ty * 8 + i];
            #pragma unroll
            for (int j = 0; j < 8; j++) bv[j] = Ws[k][tx * 8 + j];
            #pragma unroll
            for (int i = 0; i < 8; i++)
                #pragma unroll
                for (int j = 0; j < 8; j++)
                    acc[i][j] = fmaf(av[i], bv[j], acc[i][j]);
        }
        __syncthreads();
    }
    #pragma unroll
    for (int i = 0; i < 8; i++) {
        size_t m = (size_t)(m0 + ty * 8 + i);
        #pragma unroll
        for (int j = 0; j < 8; j++) {
            int n = n0 + tx * 8 + j;
            float v = acc[i][j] + bias[n];
            if (relu) v = fmaxf(v, 0.0f);
            if (res) v += res[m * D + n];
            C[m * D + n] = v;
        }
    }
}

// ================= final gather =================
__global__ __launch_bounds__(128) void k_gather(const float* __restrict__ y,
                                                const int* __restrict__ sel,
                                                float* __restrict__ out) {
    int r = blockIdx.x;              // 0..B*S-1
    int b = r >> 7, s = r & (S_SEL - 1);
    int node = b * NPG + sel[b * S_SEL + s];
    ((float4*)(out + (size_t)r * D))[threadIdx.x] =
        ((const float4*)(y + (size_t)node * D))[threadIdx.x];
}

// ================= host launcher =================
extern "C" void kernel_launch(void* const* d_in, const int* in_sizes, int n_in,
                              void* d_out, int out_size) {
    const float* x       = (const float*)d_in[0];
    const int*   eidx    = (const int*)d_in[1];
    const int*   sel     = (const int*)d_in[2];
    // d_in[3] = edge_label (unused by the reference computation)
    const float* conv_W1 = (const float*)d_in[4];
    const float* conv_b1 = (const float*)d_in[5];
    const float* conv_W2 = (const float*)d_in[6];
    const float* conv_b2 = (const float*)d_in[7];
    const float* ln1_g   = (const float*)d_in[8];
    const float* ln1_b   = (const float*)d_in[9];
    const float* ln2_g   = (const float*)d_in[10];
    const float* ln2_b   = (const float*)d_in[11];
    const float* ffn_W1  = (const float*)d_in[12];
    const float* ffn_b1  = (const float*)d_in[13];
    const float* ffn_W2  = (const float*)d_in[14];
    const float* ffn_b2  = (const float*)d_in[15];
    float* out = (float*)d_out;

    const int* src = eidx;            // edge_index[0]
    const int* dst = eidx + E_EDGES;  // edge_index[1]

    float *gx, *gh, *ga, *gb;
    unsigned* gagg;
    cudaGetSymbolAddress((void**)&gx, g_x);
    cudaGetSymbolAddress((void**)&gh, g_h);
    cudaGetSymbolAddress((void**)&ga, g_A);
    cudaGetSymbolAddress((void**)&gb, g_B);
    cudaGetSymbolAddress((void**)&gagg, g_agg);

    const int ND = N_NODES * D;

    k_init<<<ND / 256, 256>>>(x);

    for (int l = 0; l < L_LAYERS; l++) {
        k_ln<<<N_NODES, 128>>>(gx, ln1_g, ln1_b, gh);
        {
            dim3 grid(N_NODES / 128, D / 64);
            k_dualgemm<<<grid, 256>>>(gh, conv_W1 + (size_t)l * 2 * D * D,
                                      conv_b1 + (size_t)l * D, ga, gb);
        }
        {
            dim3 grid(E_EDGES / 128, D / 128);
            k_edge<<<grid, 256>>>(ga, gb, conv_W2 + (size_t)l * D * D, src, dst, gagg);
        }
        k_combine<<<ND / 256, 256>>>(conv_b2 + (size_t)l * D);
    }

    // final FFN block + gather
    k_ln<<<N_NODES, 128>>>(gx, ln2_g, ln2_b, gh);
    {
        dim3 grid(N_NODES / 128, D / 128);
        k_gemm<<<grid, 256>>>(gh, ffn_W1, ffn_b1, nullptr, ga, 1);
        k_gemm<<<grid, 256>>>(ga, ffn_W2, ffn_b2, gx, gh, 0);
    }
    k_gather<<<B_GR * S_SEL, 128>>>(gh, sel, out);
}

// round 3
// speedup vs baseline: 2.3165x; 2.3165x over previous
#include <cuda_runtime.h>
#include <cuda_bf16.h>
#include <cstdint>

// Problem constants (fixed shapes)
constexpr int N_NODES = 8192;
constexpr int D = 512;
constexpr int E_EDGES = 131072;
constexpr int B_GR = 16;
constexpr int NPG = 512;
constexpr int S_SEL = 128;
constexpr int L_LAYERS = 3;

// GEMM tiling
constexpr int BM = 128;
constexpr int BN = 256;
constexpr int BK = 32;             // k-chunk
constexpr int NCH = D / BK;        // 16 chunks
constexpr int NMAT = 11;

// smem stage layout (bytes): padded rows of 80B (32 bf16 + 16B pad)
constexpr int ROWB = 80;
constexpr int ZHI = 0;                      // 128*80 = 10240
constexpr int ZLO = 10240;
constexpr int WHI = 20480;                  // 256*80 = 20480
constexpr int WLO = 40960;
constexpr int STAGE = 61440;
constexpr int SM_IDX = 2 * STAGE;           // edge: sDst(512) + sSrc(512)
constexpr int SMEM_GEMM = 2 * STAGE;
constexpr int SMEM_EDGE = 2 * STAGE + 1024;

// -------- static device scratch --------
__device__ float    g_x[N_NODES * D];
__device__ float    g_h[N_NODES * D];
__device__ float    g_A[N_NODES * D];
__device__ float    g_B[N_NODES * D];
__device__ unsigned g_agg[N_NODES * D];
// bf16 weight images: [mat][hi/lo][n][k] row-major (k contiguous)
__device__ __align__(16) __nv_bfloat16 g_Wimg[(size_t)NMAT * 2 * D * D];

// ---------------- helpers ----------------
__device__ __forceinline__ unsigned fenc(float f) {
    unsigned b = __float_as_uint(f);
    return (b & 0x80000000u) ? ~b : (b | 0x80000000u);
}
__device__ __forceinline__ float fdec(unsigned u) {
    unsigned b = (u & 0x80000000u) ? (u & 0x7fffffffu) : ~u;
    return __uint_as_float(b);
}
__device__ __forceinline__ uint32_t smem_u32(const void* p) {
    uint32_t a;
    asm("{ .reg .u64 t; cvta.to.shared.u64 t, %1; cvt.u32.u64 %0, t; }" : "=r"(a) : "l"(p));
    return a;
}
__device__ __forceinline__ void cp16(uint32_t dst, const void* src) {
    asm volatile("cp.async.cg.shared.global [%0], [%1], 16;" :: "r"(dst), "l"(src) : "memory");
}
__device__ __forceinline__ void cp_commit() {
    asm volatile("cp.async.commit_group;" ::: "memory");
}
__device__ __forceinline__ void cp_wait0() {
    asm volatile("cp.async.wait_group 0;" ::: "memory");
}
__device__ __forceinline__ void ldm_x4(uint32_t* r, uint32_t addr) {
    asm volatile("ldmatrix.sync.aligned.m8n8.x4.shared.b16 {%0,%1,%2,%3}, [%4];"
                 : "=r"(r[0]), "=r"(r[1]), "=r"(r[2]), "=r"(r[3]) : "r"(addr));
}
__device__ __forceinline__ void mma16816(float* d, const uint32_t* a, uint32_t b0, uint32_t b1) {
    asm volatile(
        "mma.sync.aligned.m16n8k16.row.col.f32.bf16.bf16.f32 "
        "{%0,%1,%2,%3}, {%4,%5,%6,%7}, {%8,%9}, {%0,%1,%2,%3};"
        : "+f"(d[0]), "+f"(d[1]), "+f"(d[2]), "+f"(d[3])
        : "r"(a[0]), "r"(a[1]), "r"(a[2]), "r"(a[3]), "r"(b0), "r"(b1));
}
// split 2 fp32 -> packed bf16x2 hi + bf16x2 lo
__device__ __forceinline__ void split2(float f0, float f1, uint32_t& hp, uint32_t& lp) {
    uint32_t h;
    asm("cvt.rn.bf16x2.f32 %0, %1, %2;" : "=r"(h) : "f"(f1), "f"(f0));
    float h0 = __uint_as_float(h << 16);
    float h1 = __uint_as_float(h & 0xffff0000u);
    float l0 = f0 - h0, l1 = f1 - h1;
    asm("cvt.rn.bf16x2.f32 %0, %1, %2;" : "=r"(lp) : "f"(l1), "f"(l0));
    hp = h;
}
// split 16 values (from 4 float4s) and store to Z smem (two 16B lines per half)
__device__ __forceinline__ void split_store16(const float* v, char* smem, uint32_t zoff) {
    uint32_t hp[8], lp[8];
    #pragma unroll
    for (int i = 0; i < 8; i++) split2(v[2 * i], v[2 * i + 1], hp[i], lp[i]);
    *(uint4*)(smem + ZHI + zoff)      = make_uint4(hp[0], hp[1], hp[2], hp[3]);
    *(uint4*)(smem + ZHI + zoff + 16) = make_uint4(hp[4], hp[5], hp[6], hp[7]);
    *(uint4*)(smem + ZLO + zoff)      = make_uint4(lp[0], lp[1], lp[2], lp[3]);
    *(uint4*)(smem + ZLO + zoff + 16) = make_uint4(lp[4], lp[5], lp[6], lp[7]);
}
// cp.async one W k-chunk (hi+lo, 256 rows x 32 k) into stage
__device__ __forceinline__ void cp_w_chunk(char* stg, const __nv_bfloat16* whi,
                                           const __nv_bfloat16* wlo, int n0, int k0, int tid) {
    uint32_t wb = smem_u32(stg + WHI);
    #pragma unroll
    for (int i = 0; i < 8; i++) {
        int tx = tid + i * 256;
        int part = tx >> 10, row = (tx >> 2) & 255, seg = tx & 3;
        const __nv_bfloat16* src = (part ? wlo : whi) + (size_t)(n0 + row) * D + k0 + seg * 8;
        cp16(wb + part * 20480 + row * ROWB + seg * 16, src);
    }
    cp_commit();
}

// ================= init / prep / ln / combine / gather =================
__global__ void k_init(const float* __restrict__ x) {
    int i = blockIdx.x * 256 + threadIdx.x;
    g_x[i] = x[i];
    g_agg[i] = 0u;
}

// weight prep: mats 0..8: l=m/3; r0: Wd=W1top-W1bot; r1: Wb=W1bot; r2: W2^T
// mat 9: ffnW1^T ; 10: ffnW2^T.  Image [n][k] row-major bf16 hi/lo.
__global__ void k_prep(const float* __restrict__ W1, const float* __restrict__ W2,
                       const float* __restrict__ fW1, const float* __restrict__ fW2,
                       __nv_bfloat16* __restrict__ img) {
    int m = blockIdx.y;
    int e = blockIdx.x * 256 + threadIdx.x;
    int n = e & 511, k = e >> 9;
    float w;
    if (m < 9) {
        int l = m / 3, r = m % 3;
        const float* base = W1 + (size_t)l * 2 * D * D;
        if (r == 0)      w = base[(size_t)k * D + n] - base[(size_t)(D + k) * D + n];
        else if (r == 1) w = base[(size_t)(D + k) * D + n];
        else             w = W2[((size_t)l * D + k) * D + n];
    } else if (m == 9)   w = fW1[(size_t)k * D + n];
    else                 w = fW2[(size_t)k * D + n];
    __nv_bfloat16 h = __float2bfloat16(w);
    __nv_bfloat16 lo = __float2bfloat16(w - __bfloat162float(h));
    size_t idx = (size_t)n * D + k;
    img[((size_t)m * 2) * (D * D) + idx]     = h;
    img[((size_t)m * 2 + 1) * (D * D) + idx] = lo;
}

__global__ __launch_bounds__(128) void k_ln(const float* __restrict__ x,
                                            const float* __restrict__ gamma,
                                            const float* __restrict__ beta,
                                            float* __restrict__ out) {
    __shared__ float red[8];
    int row = blockIdx.x;
    int t = threadIdx.x;
    float4 v = ((const float4*)(x + (size_t)row * D))[t];
    float s = v.x + v.y + v.z + v.w;
    #pragma unroll
    for (int o = 16; o > 0; o >>= 1) s += __shfl_xor_sync(0xffffffffu, s, o);
    if ((t & 31) == 0) red[t >> 5] = s;
    __syncthreads();
    if (t == 0) red[4] = red[0] + red[1] + red[2] + red[3];
    __syncthreads();
    float mu = red[4] * (1.0f / D);
    __syncthreads();
    float dx = v.x - mu, dy = v.y - mu, dz = v.z - mu, dw = v.w - mu;
    float q = dx * dx + dy * dy + dz * dz + dw * dw;
    #pragma unroll
    for (int o = 16; o > 0; o >>= 1) q += __shfl_xor_sync(0xffffffffu, q, o);
    if ((t & 31) == 0) red[t >> 5] = q;
    __syncthreads();
    if (t == 0) red[4] = red[0] + red[1] + red[2] + red[3];
    __syncthreads();
    float rstd = rsqrtf(red[4] * (1.0f / D) + 1e-5f);
    float4 g4 = ((const float4*)gamma)[t];
    float4 b4 = ((const float4*)beta)[t];
    float4 o4;
    o4.x = dx * rstd * g4.x + b4.x;
    o4.y = dy * rstd * g4.y + b4.y;
    o4.z = dz * rstd * g4.z + b4.z;
    o4.w = dw * rstd * g4.w + b4.w;
    ((float4*)(out + (size_t)row * D))[t] = o4;
}

__global__ void k_combine(const float* __restrict__ b2) {
    int i = blockIdx.x * 256 + threadIdx.x;
    unsigned u = g_agg[i];
    g_agg[i] = 0u;
    float v = (u == 0u) ? 0.0f : (fdec(u) + b2[i & (D - 1)]);
    g_x[i] = fmaxf(v, 0.0f) + g_x[i];
}

__global__ __launch_bounds__(128) void k_gather(const float* __restrict__ y,
                                                const int* __restrict__ sel,
                                                float* __restrict__ out) {
    int r = blockIdx.x;
    int b = r >> 7, s = r & (S_SEL - 1);
    int node = b * NPG + sel[b * S_SEL + s];
    ((float4*)(out + (size_t)r * D))[threadIdx.x] =
        ((const float4*)(y + (size_t)node * D))[threadIdx.x];
}

// ================= dense GEMM: out = op(H @ Wimg + bias [+res]) =================
// grid(x = N/256, y = M/128), 256 threads
__global__ __launch_bounds__(256, 1) void k_mma_gemm(
    const float* __restrict__ Hm,
    const __nv_bfloat16* __restrict__ whi,
    const __nv_bfloat16* __restrict__ wlo,
    const float* __restrict__ bias,
    const float* __restrict__ res,
    float* __restrict__ out,
    int relu)
{
    extern __shared__ char smem[];
    int tid = threadIdx.x;
    int n0 = blockIdx.x * BN;
    int m0 = blockIdx.y * BM;

    int lane = tid & 31, wm = (tid >> 5) & 1, wn = tid >> 6;
    int zrow = tid >> 1, half = tid & 1;
    const float* hrow = Hm + (size_t)(m0 + zrow) * D + half * 16;
    uint32_t zoff = zrow * ROWB + half * 32;

    uint32_t aoff = (uint32_t)(wm * 64 + (lane & 7) + ((lane >> 3) & 1) * 8) * ROWB
                  + ((lane >> 4) & 1) * 16;
    uint32_t boff = (uint32_t)(wn * 64 + (lane & 7) + ((lane >= 16) ? 8 : 0)) * ROWB
                  + ((lane >> 3) & 1) * 16;

    float acc[4][8][4] = {};

    // prologue: stage 0
    cp_w_chunk(smem, whi, wlo, n0, 0, tid);
    {
        float v[16];
        #pragma unroll
        for (int i = 0; i < 4; i++) *(float4*)(v + 4 * i) = *(const float4*)(hrow + 4 * i);
        split_store16(v, smem, zoff);
    }
    cp_wait0();
    __syncthreads();

    for (int c = 0; c < NCH; c++) {
        char* stg = smem + (c & 1) * STAGE;
        char* nstg = smem + ((c + 1) & 1) * STAGE;
        uint32_t zhi = smem_u32(stg + ZHI), zlo = smem_u32(stg + ZLO);
        uint32_t whb = smem_u32(stg + WHI), wlb = smem_u32(stg + WLO);

        float v[16];
        if (c + 1 < NCH) {
            cp_w_chunk(nstg, whi, wlo, n0, (c + 1) * BK, tid);
            const float* p = hrow + (c + 1) * BK;
            #pragma unroll
            for (int i = 0; i < 4; i++) *(float4*)(v + 4 * i) = *(const float4*)(p + 4 * i);
        }

        #pragma unroll
        for (int kh = 0; kh < 2; kh++) {
            uint32_t ah[4][4], al[4][4];
            #pragma unroll
            for (int mf = 0; mf < 4; mf++) {
                ldm_x4(ah[mf], zhi + aoff + mf * 16 * ROWB + kh * 32);
                ldm_x4(al[mf], zlo + aoff + mf * 16 * ROWB + kh * 32);
            }
            #pragma unroll
            for (int np = 0; np < 4; np++) {
                uint32_t bh[4], bl[4];
                ldm_x4(bh, whb + boff + np * 16 * ROWB + kh * 32);
                ldm_x4(bl, wlb + boff + np * 16 * ROWB + kh * 32);
                #pragma unroll
                for (int j = 0; j < 2; j++) {
                    #pragma unroll
                    for (int mf = 0; mf < 4; mf++) {
                        float* d = acc[mf][np * 2 + j];
                        mma16816(d, ah[mf], bh[2 * j], bh[2 * j + 1]);
                        mma16816(d, al[mf], bh[2 * j], bh[2 * j + 1]);
                        mma16816(d, ah[mf], bl[2 * j], bl[2 * j + 1]);
                    }
                }
            }
        }
        if (c + 1 < NCH) split_store16(v, nstg, zoff);
        cp_wait0();
        __syncthreads();
    }

    // epilogue
    #pragma unroll
    for (int mf = 0; mf < 4; mf++) {
        int r0 = m0 + wm * 64 + mf * 16 + (lane >> 2);
        int colb = n0 + wn * 64 + 2 * (lane & 3);
        #pragma unroll
        for (int nf = 0; nf < 8; nf++) {
            int col = colb + nf * 8;
            float2 bv = bias ? *(const float2*)(bias + col) : make_float2(0.f, 0.f);
            float c0 = acc[mf][nf][0] + bv.x, c1 = acc[mf][nf][1] + bv.y;
            float c2 = acc[mf][nf][2] + bv.x, c3 = acc[mf][nf][3] + bv.y;
            if (relu) {
                c0 = fmaxf(c0, 0.f); c1 = fmaxf(c1, 0.f);
                c2 = fmaxf(c2, 0.f); c3 = fmaxf(c3, 0.f);
            }
            if (res) {
                float2 r1v = *(const float2*)(res + (size_t)r0 * D + col);
                float2 r2v = *(const float2*)(res + (size_t)(r0 + 8) * D + col);
                c0 += r1v.x; c1 += r1v.y; c2 += r2v.x; c3 += r2v.y;
            }
            *(float2*)(out + (size_t)r0 * D + col) = make_float2(c0, c1);
            *(float2*)(out + (size_t)(r0 + 8) * D + col) = make_float2(c2, c3);
        }
    }
}

// ================= edge GEMM: relu(A[dst]+B[src]) @ W2img -> atomicMax =================
// grid(x = N/256 = 2, y = E/128 = 1024), 256 threads
__global__ __launch_bounds__(256, 1) void k_mma_edge(
    const __nv_bfloat16* __restrict__ whi,
    const __nv_bfloat16* __restrict__ wlo,
    const int* __restrict__ src,
    const int* __restrict__ dst,
    unsigned* __restrict__ agg)
{
    extern __shared__ char smem[];
    int tid = threadIdx.x;
    int n0 = blockIdx.x * BN;
    int e0 = blockIdx.y * BM;

    int* sDst = (int*)(smem + SM_IDX);
    int* sSrc = (int*)(smem + SM_IDX + 512);
    if (tid < 128) sDst[tid] = dst[e0 + tid];
    else           sSrc[tid - 128] = src[e0 + tid - 128];

    int lane = tid & 31, wm = (tid >> 5) & 1, wn = tid >> 6;
    int zrow = tid >> 1, half = tid & 1;
    uint32_t zoff = zrow * ROWB + half * 32;

    uint32_t aoff = (uint32_t)(wm * 64 + (lane & 7) + ((lane >> 3) & 1) * 8) * ROWB
                  + ((lane >> 4) & 1) * 16;
    uint32_t boff = (uint32_t)(wn * 64 + (lane & 7) + ((lane >= 16) ? 8 : 0)) * ROWB
                  + ((lane >> 3) & 1) * 16;

    float acc[4][8][4] = {};

    cp_w_chunk(smem, whi, wlo, n0, 0, tid);
    __syncthreads();   // sDst/sSrc visible
    const float* ap = g_A + (size_t)sDst[zrow] * D + half * 16;
    const float* bp = g_B + (size_t)sSrc[zrow] * D + half * 16;
    {
        float v[16];
        #pragma unroll
        for (int i = 0; i < 4; i++) {
            float4 a = *(const float4*)(ap + 4 * i);
            float4 b = *(const float4*)(bp + 4 * i);
            v[4 * i + 0] = fmaxf(a.x + b.x, 0.f); v[4 * i + 1] = fmaxf(a.y + b.y, 0.f);
            v[4 * i + 2] = fmaxf(a.z + b.z, 0.f); v[4 * i + 3] = fmaxf(a.w + b.w, 0.f);
        }
        split_store16(v, smem, zoff);
    }
    cp_wait0();
    __syncthreads();

    for (int c = 0; c < NCH; c++) {
        char* stg = smem + (c & 1) * STAGE;
        char* nstg = smem + ((c + 1) & 1) * STAGE;
        uint32_t zhi = smem_u32(stg + ZHI), zlo = smem_u32(stg + ZLO);
        uint32_t whb = smem_u32(stg + WHI), wlb = smem_u32(stg + WLO);

        float v[16];
        if (c + 1 < NCH) {
            cp_w_chunk(nstg, whi, wlo, n0, (c + 1) * BK, tid);
            int k1 = (c + 1) * BK;
            #pragma unroll
            for (int i = 0; i < 4; i++) {
                float4 a = *(const float4*)(ap + k1 + 4 * i);
                float4 b = *(const float4*)(bp + k1 + 4 * i);
                v[4 * i + 0] = fmaxf(a.x + b.x, 0.f); v[4 * i + 1] = fmaxf(a.y + b.y, 0.f);
                v[4 * i + 2] = fmaxf(a.z + b.z, 0.f); v[4 * i + 3] = fmaxf(a.w + b.w, 0.f);
            }
        }

        #pragma unroll
        for (int kh = 0; kh < 2; kh++) {
            uint32_t ah[4][4], al[4][4];
            #pragma unroll
            for (int mf = 0; mf < 4; mf++) {
                ldm_x4(ah[mf], zhi + aoff + mf * 16 * ROWB + kh * 32);
                ldm_x4(al[mf], zlo + aoff + mf * 16 * ROWB + kh * 32);
            }
            #pragma unroll
            for (int np = 0; np < 4; np++) {
                uint32_t bh[4], bl[4];
                ldm_x4(bh, whb + boff + np * 16 * ROWB + kh * 32);
                ldm_x4(bl, wlb + boff + np * 16 * ROWB + kh * 32);
                #pragma unroll
                for (int j = 0; j < 2; j++) {
                    #pragma unroll
                    for (int mf = 0; mf < 4; mf++) {
                        float* d = acc[mf][np * 2 + j];
                        mma16816(d, ah[mf], bh[2 * j], bh[2 * j + 1]);
                        mma16816(d, al[mf], bh[2 * j], bh[2 * j + 1]);
                        mma16816(d, ah[mf], bl[2 * j], bl[2 * j + 1]);
                    }
                }
            }
        }
        if (c + 1 < NCH) split_store16(v, nstg, zoff);
        cp_wait0();
        __syncthreads();
    }

    // epilogue: atomic segment-max
    #pragma unroll
    for (int mf = 0; mf < 4; mf++) {
        int r0 = wm * 64 + mf * 16 + (lane >> 2);
        unsigned* p0 = agg + (size_t)sDst[r0] * D + n0 + wn * 64 + 2 * (lane & 3);
        unsigned* p1 = agg + (size_t)sDst[r0 + 8] * D + n0 + wn * 64 + 2 * (lane & 3);
        #pragma unroll
        for (int nf = 0; nf < 8; nf++) {
            atomicMax(p0 + nf * 8,     fenc(acc[mf][nf][0]));
            atomicMax(p0 + nf * 8 + 1, fenc(acc[mf][nf][1]));
            atomicMax(p1 + nf * 8,     fenc(acc[mf][nf][2]));
            atomicMax(p1 + nf * 8 + 1, fenc(acc[mf][nf][3]));
        }
    }
}

// ================= host launcher =================
extern "C" void kernel_launch(void* const* d_in, const int* in_sizes, int n_in,
                              void* d_out, int out_size) {
    const float* x       = (const float*)d_in[0];
    const int*   eidx    = (const int*)d_in[1];
    const int*   sel     = (const int*)d_in[2];
    const float* conv_W1 = (const float*)d_in[4];
    const float* conv_b1 = (const float*)d_in[5];
    const float* conv_W2 = (const float*)d_in[6];
    const float* conv_b2 = (const float*)d_in[7];
    const float* ln1_g   = (const float*)d_in[8];
    const float* ln1_b   = (const float*)d_in[9];
    const float* ln2_g   = (const float*)d_in[10];
    const float* ln2_b   = (const float*)d_in[11];
    const float* ffn_W1  = (const float*)d_in[12];
    const float* ffn_b1  = (const float*)d_in[13];
    const float* ffn_W2  = (const float*)d_in[14];
    const float* ffn_b2  = (const float*)d_in[15];
    float* out = (float*)d_out;

    const int* src = eidx;
    const int* dst = eidx + E_EDGES;

    float *gx, *gh, *ga, *gb;
    unsigned* gagg;
    __nv_bfloat16* gw;
    cudaGetSymbolAddress((void**)&gx, g_x);
    cudaGetSymbolAddress((void**)&gh, g_h);
    cudaGetSymbolAddress((void**)&ga, g_A);
    cudaGetSymbolAddress((void**)&gb, g_B);
    cudaGetSymbolAddress((void**)&gagg, g_agg);
    cudaGetSymbolAddress((void**)&gw, g_Wimg);

    cudaFuncSetAttribute(k_mma_gemm, cudaFuncAttributeMaxDynamicSharedMemorySize, SMEM_GEMM);
    cudaFuncSetAttribute(k_mma_edge, cudaFuncAttributeMaxDynamicSharedMemorySize, SMEM_EDGE);

    auto WH = [&](int m) { return gw + (size_t)m * 2 * (D * D); };
    auto WL = [&](int m) { return gw + ((size_t)m * 2 + 1) * (D * D); };

    const int ND = N_NODES * D;

    k_init<<<ND / 256, 256>>>(x);
    {
        dim3 grid(1024, NMAT);
        k_prep<<<grid, 256>>>(conv_W1, conv_W2, ffn_W1, ffn_W2, gw);
    }

    dim3 ggemm(D / BN, N_NODES / BM);   // (2, 64)
    dim3 gedge(D / BN, E_EDGES / BM);   // (2, 1024)

    for (int l = 0; l < L_LAYERS; l++) {
        k_ln<<<N_NODES, 128>>>(gx, ln1_g, ln1_b, gh);
        k_mma_gemm<<<ggemm, 256, SMEM_GEMM>>>(gh, WH(l * 3 + 0), WL(l * 3 + 0),
                                              conv_b1 + (size_t)l * D, nullptr, ga, 0);
        k_mma_gemm<<<ggemm, 256, SMEM_GEMM>>>(gh, WH(l * 3 + 1), WL(l * 3 + 1),
                                              nullptr, nullptr, gb, 0);
        k_mma_edge<<<gedge, 256, SMEM_EDGE>>>(WH(l * 3 + 2), WL(l * 3 + 2), src, dst, gagg);
        k_combine<<<ND / 256, 256>>>(conv_b2 + (size_t)l * D);
    }

    k_ln<<<N_NODES, 128>>>(gx, ln2_g, ln2_b, gh);
    k_mma_gemm<<<ggemm, 256, SMEM_GEMM>>>(gh, WH(9), WL(9), ffn_b1, nullptr, ga, 1);
    k_mma_gemm<<<ggemm, 256, SMEM_GEMM>>>(ga, WH(10), WL(10), ffn_b2, gx, gh, 0);
    k_gather<<<B_GR * S_SEL, 128>>>(gh, sel, out);
}